// round 8
// baseline (speedup 1.0000x reference)
#include <cuda_runtime.h>
#include <cuda_bf16.h>
#include <stdint.h>

// ---------------- problem dims ----------------
#define BATCH 8
#define CIN   2
#define HH    64
#define WW    64
#define TT    200
#define NCH   7      // ceil(200/32) chunks of 32 timesteps (tail garbage is causal-safe)
#define C1    8
#define C2    8
#define NTAP1 (CIN * 25)   // 50
#define NTAP2 (C1 * 9)     // 72

// fp32 correctly-rounded decay constants
#define D1 0.36787944117144233f   // exp(-1)    : tau=1 (psp1, ref1)
#define D2 0.60653065971263342f   // exp(-1/2)  : tau=2 (psp2, ref2)
#define D3 0.77880078307140487f   // exp(-1/4)  : tau=4 (psp3, ref3)

// LUT entry stride: 9 floats (36B). gcd(9,32)=1 -> bank starts cover all 32
// banks as m varies, breaking the degree-8 conflicts of the 32B-stride layout.
#define ESTR 9
#define L1_SLICES 6                 // 2 cin x 3 groups of 8 taps (tap 24 in regs)
#define L2_SLICES 8                 // 8 cin x 1 group of 8 taps (tap 8 via smem ex)
#define SMEM1_FLOATS (L1_SLICES * 256 * ESTR)
#define SMEM2_FLOATS (L2_SLICES * 256 * ESTR + 64)

// ---------------- bit-packed intermediates ----------------
__device__ uint32_t g_xbits[BATCH * NCH * CIN * HH * WW];  // 1.75 MB
__device__ uint32_t g_s1  [BATCH * NCH * C1  * HH * WW];   // 7 MB
__device__ uint32_t g_s2  [BATCH * NCH * C2  * HH * WW];   // 7 MB

// 8x32 -> per-j byte extraction for one jg (8 timesteps):
// gather byte jg of 8 tap-words, then 8x8 bit transpose.
// result: byte jj = 8 tap-bits at timestep jg*8+jj.
__device__ __forceinline__ unsigned long long t8x8(const uint32_t* w, int jg) {
    uint32_t s = (uint32_t)jg | (((uint32_t)jg + 4) << 4);
    uint32_t r01 = __byte_perm(w[0], w[1], s);
    uint32_t r23 = __byte_perm(w[2], w[3], s);
    uint32_t r45 = __byte_perm(w[4], w[5], s);
    uint32_t r67 = __byte_perm(w[6], w[7], s);
    uint32_t lo = __byte_perm(r01, r23, 0x5410);
    uint32_t hi = __byte_perm(r45, r67, 0x5410);
    unsigned long long x = (unsigned long long)lo | ((unsigned long long)hi << 32);
    unsigned long long t;
    t = (x ^ (x >> 7))  & 0x00AA00AA00AA00AAull; x = x ^ t ^ (t << 7);
    t = (x ^ (x >> 14)) & 0x0000CCCC0000CCCCull; x = x ^ t ^ (t << 14);
    t = (x ^ (x >> 28)) & 0x00000000F0F0F0F0ull; x = x ^ t ^ (t << 28);
    return x;
}

// =====================================================================
// K0: binarize + time-transpose input [b,c,h,w,t] -> bitmasks
// =====================================================================
__global__ void k_binarize(const float* __restrict__ x) {
    int tid = blockIdx.x * blockDim.x + threadIdx.x;
    if (tid >= BATCH * CIN * HH * WW * NCH) return;
    int k   = tid % NCH;
    int pix = tid / NCH;
    int w = pix % WW; int t1 = pix / WW;
    int h = t1 % HH;  t1 /= HH;
    int c = t1 % CIN; int b = t1 / CIN;
    const float* p = x + (size_t)pix * TT + k * 32;
    int n = min(32, TT - k * 32);
    uint32_t bits = 0;
    for (int i = 0; i < n; i++) bits |= (p[i] > 0.5f) ? (1u << i) : 0u;
    g_xbits[(((b * NCH + k) * CIN + c) * HH + h) * WW + w] = bits;
}

// =====================================================================
// K1: layer 1.  u = IIR_1(conv5x5(xbits)); spike(th=30, dref=D1)
// subset-sum LUT (stride-9 entries): per jj, 8 LDS.32 + 8 FADD.
// =====================================================================
__global__ void __launch_bounds__(128) k_layer1(const float* __restrict__ w1) {
    extern __shared__ float dyn[];
    float* lut = dyn;                        // [slice(6)][m(256)][stride 9, 8 oc used]
    {
        int t = threadIdx.x;
        if (t < 48) {
            int c = t / 24, g = (t / 8) % 3, o = t & 7;
            int gi = c * 3 + g;
            float wr[8];
#pragma unroll
            for (int p = 0; p < 8; p++) wr[p] = w1[o * NTAP1 + c * 25 + g * 8 + p];
            lut[(gi * 256 + 0) * ESTR + o] = 0.f;
            for (int m = 1; m < 256; m++) {
                int pm = 31 - __clz(m);
                lut[(gi * 256 + m) * ESTR + o] =
                    lut[(gi * 256 + (m ^ (1 << pm))) * ESTR + o] + wr[pm];
            }
        }
    }
    __syncthreads();

    int tid = blockIdx.x * blockDim.x + threadIdx.x;
    int w = tid % WW; int t1 = tid / WW;
    int h = t1 % HH;  int b = t1 / HH;

    // tap-24 weights in registers (uniform loads)
    float exr[2][8];
#pragma unroll
    for (int c = 0; c < 2; c++)
#pragma unroll
        for (int o = 0; o < 8; o++) exr[c][o] = w1[o * NTAP1 + c * 25 + 24];

    float a[C1], r[C1];
#pragma unroll
    for (int o = 0; o < C1; o++) { a[o] = 0.f; r[o] = 0.f; }

    for (int k = 0; k < NCH; k++) {
        uint32_t bits[NTAP1];
#pragma unroll
        for (int c = 0; c < CIN; c++)
#pragma unroll
            for (int dy = 0; dy < 5; dy++)
#pragma unroll
                for (int dx = 0; dx < 5; dx++) {
                    int hh = h + dy - 2, ww = w + dx - 2;
                    uint32_t v = 0;
                    if (hh >= 0 && hh < HH && ww >= 0 && ww < WW)
                        v = g_xbits[(((b * NCH + k) * CIN + c) * HH + hh) * WW + ww];
                    bits[(c * 5 + dy) * 5 + dx] = v;
                }

        uint32_t sb[C1];
#pragma unroll
        for (int o = 0; o < C1; o++) sb[o] = 0u;

#pragma unroll 1
        for (int jg = 0; jg < 4; jg++) {
            float acc[64];                   // [jj][oc]
#pragma unroll
            for (int i = 0; i < 64; i++) acc[i] = 0.f;
#pragma unroll 1
            for (int c = 0; c < CIN; c++) {
#pragma unroll
                for (int g = 0; g < 3; g++) {
                    int gi = c * 3 + g;
                    unsigned long long tx = t8x8(bits + c * 25 + g * 8, jg);
#pragma unroll
                    for (int jj = 0; jj < 8; jj++) {
                        int m = (int)(tx >> (8 * jj)) & 0xFF;
                        const float* e = &lut[(unsigned)((gi << 8) | m) * ESTR];
#pragma unroll
                        for (int o = 0; o < 8; o++) acc[jj * 8 + o] += e[o];
                    }
                }
                uint32_t b24 = (bits[c * 25 + 24] >> (jg * 8)) & 0xFF;
#pragma unroll
                for (int jj = 0; jj < 8; jj++)
                    if ((b24 >> jj) & 1u) {
#pragma unroll
                        for (int o = 0; o < 8; o++) acc[jj * 8 + o] += exr[c][o];
                    }
            }
#pragma unroll
            for (int jj = 0; jj < 8; jj++) {
                int j = jg * 8 + jj;
#pragma unroll
                for (int o = 0; o < C1; o++) {
                    a[o] = D1 * a[o] + acc[jj * 8 + o];
                    float v = a[o] + r[o];
                    bool hd = v >= 30.0f;
                    sb[o] |= hd ? (1u << j) : 0u;
                    r[o] = D1 * r[o] - (hd ? 30.0f : 0.0f);
                }
            }
        }
#pragma unroll
        for (int o = 0; o < C1; o++)
            g_s1[(((b * NCH + k) * C1 + o) * HH + h) * WW + w] = sb[o];
    }
}

// =====================================================================
// K2: layer 2.  u = IIR_2(conv3x3(s1bits)); spike(th=50, dref=D2)
// 8 channels x (8 taps via stride-9 LUT + tap8 predicated from smem)
// =====================================================================
__global__ void __launch_bounds__(128) k_layer2(const float* __restrict__ w2) {
    extern __shared__ float dyn[];
    float* lut = dyn;                        // [c(8)][m(256)][stride 9]
    float* ex  = dyn + L2_SLICES * 256 * ESTR;  // [c(8)][oc(8)]
    {
        int t = threadIdx.x;
        if (t < 64) {
            int c = t >> 3, o = t & 7;
            float wr[8];
#pragma unroll
            for (int p = 0; p < 8; p++) wr[p] = w2[o * NTAP2 + c * 9 + p];
            ex[c * 8 + o] = w2[o * NTAP2 + c * 9 + 8];
            lut[(c * 256 + 0) * ESTR + o] = 0.f;
            for (int m = 1; m < 256; m++) {
                int pm = 31 - __clz(m);
                lut[(c * 256 + m) * ESTR + o] =
                    lut[(c * 256 + (m ^ (1 << pm))) * ESTR + o] + wr[pm];
            }
        }
    }
    __syncthreads();

    int tid = blockIdx.x * blockDim.x + threadIdx.x;
    int w = tid % WW; int t1 = tid / WW;
    int h = t1 % HH;  int b = t1 / HH;

    float a[C2], r[C2];
#pragma unroll
    for (int o = 0; o < C2; o++) { a[o] = 0.f; r[o] = 0.f; }

    for (int k = 0; k < NCH; k++) {
        uint32_t bits[NTAP2];
#pragma unroll
        for (int c = 0; c < C1; c++)
#pragma unroll
            for (int dy = 0; dy < 3; dy++)
#pragma unroll
                for (int dx = 0; dx < 3; dx++) {
                    int hh = h + dy - 1, ww = w + dx - 1;
                    uint32_t v = 0;
                    if (hh >= 0 && hh < HH && ww >= 0 && ww < WW)
                        v = g_s1[(((b * NCH + k) * C1 + c) * HH + hh) * WW + ww];
                    bits[(c * 3 + dy) * 3 + dx] = v;
                }

        uint32_t sb[C2];
#pragma unroll
        for (int o = 0; o < C2; o++) sb[o] = 0u;

#pragma unroll 1
        for (int jg = 0; jg < 4; jg++) {
            float acc[64];                   // [jj][oc]
#pragma unroll
            for (int i = 0; i < 64; i++) acc[i] = 0.f;
#pragma unroll 1
            for (int c = 0; c < C1; c++) {
                unsigned long long tx = t8x8(bits + c * 9, jg);
#pragma unroll
                for (int jj = 0; jj < 8; jj++) {
                    int m = (int)(tx >> (8 * jj)) & 0xFF;
                    const float* e = &lut[(unsigned)((c << 8) | m) * ESTR];
#pragma unroll
                    for (int o = 0; o < 8; o++) acc[jj * 8 + o] += e[o];
                }
                float exv[8];
#pragma unroll
                for (int o = 0; o < 8; o++) exv[o] = ex[c * 8 + o];  // broadcast LDS
                uint32_t b8 = (bits[c * 9 + 8] >> (jg * 8)) & 0xFF;
#pragma unroll
                for (int jj = 0; jj < 8; jj++)
                    if ((b8 >> jj) & 1u) {
#pragma unroll
                        for (int o = 0; o < 8; o++) acc[jj * 8 + o] += exv[o];
                    }
            }
#pragma unroll
            for (int jj = 0; jj < 8; jj++) {
                int j = jg * 8 + jj;
#pragma unroll
                for (int o = 0; o < C2; o++) {
                    a[o] = D2 * a[o] + acc[jj * 8 + o];
                    float v = a[o] + r[o];
                    bool hd = v >= 50.0f;
                    sb[o] |= hd ? (1u << j) : 0u;
                    r[o] = D2 * r[o] - (hd ? 50.0f : 0.0f);
                }
            }
        }
#pragma unroll
        for (int o = 0; o < C2; o++)
            g_s2[(((b * NCH + k) * C2 + o) * HH + h) * WW + w] = sb[o];
    }
}

// =====================================================================
// K3: layer 3 (proven R5/R7 version, 84.8us).
//   u3 = IIR_4(convT2x2(s2bits)) + IIR_1(bilinear2x(xbits)); spike(th=100, dref=D3)
// =====================================================================
__global__ void __launch_bounds__(128) k_layer3(const float* __restrict__ wup,
                                                float* __restrict__ out) {
    __shared__ float swu[64];
    if (threadIdx.x < 64) swu[threadIdx.x] = wup[threadIdx.x];
    __syncthreads();

    int tid = blockIdx.x * blockDim.x + threadIdx.x;
    int wo = tid & 127; int t1 = tid >> 7;
    int ho = t1 & 127;  int b  = t1 >> 7;
    int hi = ho >> 1, wi = wo >> 1;
    int pa = ho & 1,  pb = wo & 1;

    int r0, r1, c0, c1; float wr0, wr1, wc0, wc1;
    if (!pa) { r0 = (hi > 0) ? hi - 1 : 0;  r1 = hi; wr0 = 0.25f; wr1 = 0.75f; }
    else     { r0 = hi; r1 = (hi < 63) ? hi + 1 : 63; wr0 = 0.75f; wr1 = 0.25f; }
    if (!pb) { c0 = (wi > 0) ? wi - 1 : 0;  c1 = wi; wc0 = 0.25f; wc1 = 0.75f; }
    else     { c0 = wi; c1 = (wi < 63) ? wi + 1 : 63; wc0 = 0.75f; wc1 = 0.25f; }
    float tw00 = wr0 * wc0, tw01 = wr0 * wc1, tw10 = wr1 * wc0, tw11 = wr1 * wc1;

    int lane = threadIdx.x & 31;
    int wo0  = wo & ~31;

    float a[2], p[2], rr[2];
#pragma unroll
    for (int o = 0; o < 2; o++) { a[o] = 0.f; p[o] = 0.f; rr[o] = 0.f; }

    for (int k = 0; k < NCH; k++) {
        uint32_t s2b[C2];
#pragma unroll
        for (int c = 0; c < C2; c++)
            s2b[c] = g_s2[(((b * NCH + k) * C2 + c) * HH + hi) * WW + wi];
        uint32_t xb00[2], xb01[2], xb10[2], xb11[2];
#pragma unroll
        for (int c = 0; c < 2; c++) {
            const uint32_t* xp = g_xbits + (size_t)(((b * NCH + k) * CIN) + c) * HH * WW;
            xb00[c] = xp[r0 * WW + c0]; xb01[c] = xp[r0 * WW + c1];
            xb10[c] = xp[r1 * WW + c0]; xb11[c] = xp[r1 * WW + c1];
        }
#pragma unroll 1
        for (int o = 0; o < 2; o++) {
            float sA[32], sX[32];
#pragma unroll
            for (int j = 0; j < 32; j++) { sA[j] = 0.f; sX[j] = 0.f; }
#pragma unroll
            for (int c = 0; c < C2; c++) {
                float wv = swu[((o * 8 + c) * 2 + (1 - pa)) * 2 + (1 - pb)];
                uint32_t bw = s2b[c];
#pragma unroll
                for (int j = 0; j < 32; j++)
                    if (bw & (1u << j)) sA[j] += wv;
            }
            {
                uint32_t bw = xb00[o];
#pragma unroll
                for (int j = 0; j < 32; j++) if (bw & (1u << j)) sX[j] += tw00;
            }
            {
                uint32_t bw = xb01[o];
#pragma unroll
                for (int j = 0; j < 32; j++) if (bw & (1u << j)) sX[j] += tw01;
            }
            {
                uint32_t bw = xb10[o];
#pragma unroll
                for (int j = 0; j < 32; j++) if (bw & (1u << j)) sX[j] += tw10;
            }
            {
                uint32_t bw = xb11[o];
#pragma unroll
                for (int j = 0; j < 32; j++) if (bw & (1u << j)) sX[j] += tw11;
            }
            uint32_t sb = 0;
            float av = a[o], pv = p[o], rv = rr[o];
#pragma unroll
            for (int j = 0; j < 32; j++) {
                av = D3 * av + sA[j];
                pv = D1 * pv + sX[j];
                float v = av + pv + rv;
                bool hd = v >= 100.0f;
                sb |= hd ? (1u << j) : 0u;
                rv = D3 * rv - (hd ? 100.0f : 0.0f);
            }
            a[o] = av; p[o] = pv; rr[o] = rv;

            size_t rowbase = ((size_t)((b * 2 + o) * 128 + ho) * 128 + wo0) * TT;
            int t = k * 32 + lane;
#pragma unroll
            for (int pl = 0; pl < 32; pl++) {
                uint32_t wv = __shfl_sync(0xffffffffu, sb, pl);
                if (t < TT)
                    out[rowbase + (size_t)pl * TT + t] = ((wv >> lane) & 1u) ? 1.0f : 0.0f;
            }
        }
    }
}

// =====================================================================
extern "C" void kernel_launch(void* const* d_in, const int* in_sizes, int n_in,
                              void* d_out, int out_size) {
    const float* x   = (const float*)d_in[0];
    const float* w1  = (const float*)d_in[1];
    const float* w2  = (const float*)d_in[2];
    const float* wup = (const float*)d_in[3];
    float* out = (float*)d_out;

    int smem1 = SMEM1_FLOATS * 4;   // 55,296 B
    int smem2 = SMEM2_FLOATS * 4;   // 73,984 B
    cudaFuncSetAttribute(k_layer1, cudaFuncAttributeMaxDynamicSharedMemorySize, smem1);
    cudaFuncSetAttribute(k_layer2, cudaFuncAttributeMaxDynamicSharedMemorySize, smem2);

    int n0 = BATCH * CIN * HH * WW * NCH;
    k_binarize<<<(n0 + 255) / 256, 256>>>(x);
    k_layer1<<<(BATCH * HH * WW) / 128, 128, smem1>>>(w1);      // 256 blocks
    k_layer2<<<(BATCH * HH * WW) / 128, 128, smem2>>>(w2);      // 256 blocks
    k_layer3<<<(BATCH * 128 * 128) / 128, 128>>>(wup, out);     // 1024 blocks
}